// round 4
// baseline (speedup 1.0000x reference)
#include <cuda_runtime.h>
#include <math.h>
#include <stdint.h>

// Problem constants
#define B_    4
#define S_    2048
#define D_    1024
#define H_    16
#define DK_   64
#define DOUT_ 1024
#define MROWS (B_ * S_)   // 8192

// Q pre-scale: 1/sqrt(64) * log2(e)  (folded so softmax uses exp2 directly)
#define QSCALE 0.18033688011112042f

// Scratch, stored as tf32 bit patterns (uint32)
__device__ uint32_t g_Q[(size_t)B_ * H_ * S_ * DK_];    // [B,H,S,DK] tf32, pre-scaled
__device__ uint32_t g_K[(size_t)B_ * H_ * S_ * DK_];    // tf32
__device__ uint32_t g_V[(size_t)B_ * H_ * S_ * DK_];    // tf32
__device__ uint32_t g_cat[(size_t)B_ * S_ * H_ * DK_];  // [B,S,H*DK] tf32

// ---------------------------------------------------------------------------
// Helpers
// ---------------------------------------------------------------------------
__device__ __forceinline__ uint32_t f2tf(float f) {
    uint32_t u;
    asm("cvt.rna.tf32.f32 %0, %1;" : "=r"(u) : "f"(f));
    return u;
}

__device__ __forceinline__ void mma_tf32(float* d,
                                         uint32_t a0, uint32_t a1, uint32_t a2, uint32_t a3,
                                         uint32_t b0, uint32_t b1) {
    asm volatile(
        "mma.sync.aligned.m16n8k8.row.col.f32.tf32.tf32.f32 "
        "{%0,%1,%2,%3}, {%4,%5,%6,%7}, {%8,%9}, {%0,%1,%2,%3};"
        : "+f"(d[0]), "+f"(d[1]), "+f"(d[2]), "+f"(d[3])
        : "r"(a0), "r"(a1), "r"(a2), "r"(a3), "r"(b0), "r"(b1));
}

#define XS_STR 36
#define WS_STR 72

// ---------------------------------------------------------------------------
// Kernel 1: merged QKV projection. One block: 128 rows x head h x {Q,K,V}.
// A-fragments reused across the 3 weight matrices. grid=(64,16), 256 thr.
// Outputs stored as tf32 bits; Q pre-scaled by QSCALE.
// ---------------------------------------------------------------------------
__global__ __launch_bounds__(256) void qkv3_kernel(
    const float* __restrict__ x,
    const float* __restrict__ Wq, const float* __restrict__ bq,
    const float* __restrict__ Wk, const float* __restrict__ bk,
    const float* __restrict__ Wv, const float* __restrict__ bv)
{
    __shared__ uint32_t Xs[128 * XS_STR];      // [m][k]
    __shared__ uint32_t Ws[3][32 * WS_STR];    // [type][k][n]

    const int h  = blockIdx.y;
    const int m0 = blockIdx.x * 128;
    const int tid  = threadIdx.x;
    const int warp = tid >> 5;
    const int lane = tid & 31;
    const int gid  = lane >> 2;
    const int t4   = lane & 3;
    const int wm   = warp >> 1;    // 0..3 : 32 M-rows
    const int wn   = warp & 1;     // 0..1 : 32 N-cols

    const float* Wt[3] = { Wq + (size_t)h * D_ * DK_,
                           Wk + (size_t)h * D_ * DK_,
                           Wv + (size_t)h * D_ * DK_ };

    float acc[3][2][4][4];
#pragma unroll
    for (int t = 0; t < 3; t++)
#pragma unroll
        for (int mt = 0; mt < 2; mt++)
#pragma unroll
            for (int nt = 0; nt < 4; nt++)
#pragma unroll
                for (int j = 0; j < 4; j++) acc[t][mt][nt][j] = 0.f;

    for (int k0 = 0; k0 < D_; k0 += 32) {
        // X tile [128 x 32]
#pragma unroll
        for (int L = 0; L < 4; L++) {
            int lin = tid + L * 256;
            int row = lin >> 3;
            int c4  = (lin & 7) * 4;
            float4 v = *(const float4*)(x + (size_t)(m0 + row) * D_ + k0 + c4);
            Xs[row * XS_STR + c4 + 0] = f2tf(v.x);
            Xs[row * XS_STR + c4 + 1] = f2tf(v.y);
            Xs[row * XS_STR + c4 + 2] = f2tf(v.z);
            Xs[row * XS_STR + c4 + 3] = f2tf(v.w);
        }
        // W tiles [3][32 x 64]
#pragma unroll
        for (int t = 0; t < 3; t++) {
#pragma unroll
            for (int L = 0; L < 2; L++) {
                int lin = tid + L * 256;
                int kr = lin >> 4;
                int n4 = (lin & 15) * 4;
                float4 w = *(const float4*)(Wt[t] + (size_t)(k0 + kr) * DK_ + n4);
                Ws[t][kr * WS_STR + n4 + 0] = f2tf(w.x);
                Ws[t][kr * WS_STR + n4 + 1] = f2tf(w.y);
                Ws[t][kr * WS_STR + n4 + 2] = f2tf(w.z);
                Ws[t][kr * WS_STR + n4 + 3] = f2tf(w.w);
            }
        }
        __syncthreads();

#pragma unroll
        for (int ks = 0; ks < 4; ks++) {
            uint32_t a[2][4];
#pragma unroll
            for (int mt = 0; mt < 2; mt++) {
                int rb = wm * 32 + mt * 16;
                a[mt][0] = Xs[(rb + gid)     * XS_STR + ks * 8 + t4];
                a[mt][1] = Xs[(rb + gid + 8) * XS_STR + ks * 8 + t4];
                a[mt][2] = Xs[(rb + gid)     * XS_STR + ks * 8 + t4 + 4];
                a[mt][3] = Xs[(rb + gid + 8) * XS_STR + ks * 8 + t4 + 4];
            }
#pragma unroll
            for (int t = 0; t < 3; t++) {
#pragma unroll
                for (int nt = 0; nt < 4; nt++) {
                    int n = wn * 32 + nt * 8 + gid;
                    uint32_t b0 = Ws[t][(ks * 8 + t4)     * WS_STR + n];
                    uint32_t b1 = Ws[t][(ks * 8 + t4 + 4) * WS_STR + n];
                    mma_tf32(acc[t][0][nt], a[0][0], a[0][1], a[0][2], a[0][3], b0, b1);
                    mma_tf32(acc[t][1][nt], a[1][0], a[1][1], a[1][2], a[1][3], b0, b1);
                }
            }
        }
        __syncthreads();
    }

    // Epilogue: +bias, (Q: *QSCALE), cvt tf32, store
    const float* bias[3] = { bq, bk, bv };
    uint32_t* outp[3] = { g_Q, g_K, g_V };
#pragma unroll
    for (int t = 0; t < 3; t++) {
#pragma unroll
        for (int nt = 0; nt < 4; nt++) {
            int bcol = wn * 32 + nt * 8 + 2 * t4;
            float bb0 = bias[t][h * DK_ + bcol];
            float bb1 = bias[t][h * DK_ + bcol + 1];
#pragma unroll
            for (int mt = 0; mt < 2; mt++) {
#pragma unroll
                for (int half = 0; half < 2; half++) {
                    int gm = m0 + wm * 32 + mt * 16 + gid + half * 8;
                    int bb = gm >> 11;
                    int s  = gm & 2047;
                    float v0 = acc[t][mt][nt][half * 2 + 0] + bb0;
                    float v1 = acc[t][mt][nt][half * 2 + 1] + bb1;
                    if (t == 0) { v0 *= QSCALE; v1 *= QSCALE; }
                    uint2 o = make_uint2(f2tf(v0), f2tf(v1));
                    *(uint2*)(outp[t] + ((size_t)(bb * H_ + h) * S_ + s) * DK_ + bcol) = o;
                }
            }
        }
    }
}

// ---------------------------------------------------------------------------
// Kernel 2: flash attention. 128 threads (4 warps), 128 q-rows per block,
// warp = 32 q-rows. Q tile persistent in smem; P kept in registers via
// shuffle repack of the S accumulator; softmax in exp2 domain (Q pre-scaled).
// ---------------------------------------------------------------------------
#define QS_STR 68
#define KS_STR 68
#define VS_STR 72
#define ATTN_SMEM_WORDS (128 * QS_STR + 64 * KS_STR + 64 * VS_STR)

__global__ __launch_bounds__(128) void attn_mma_kernel()
{
    extern __shared__ uint32_t smw[];
    uint32_t* Qs = smw;                    // [q=128][c] tf32 (persistent)
    uint32_t* Ks = Qs + 128 * QS_STR;      // [t=64][c]
    uint32_t* Vs = Ks + 64 * KS_STR;       // [t=64][c]

    const int bh = blockIdx.y;
    const int q0 = blockIdx.x * 128;
    const uint32_t* Qg = g_Q + (size_t)bh * S_ * DK_;
    const uint32_t* Kg = g_K + (size_t)bh * S_ * DK_;
    const uint32_t* Vg = g_V + (size_t)bh * S_ * DK_;

    const int tid  = threadIdx.x;
    const int warp = tid >> 5;
    const int lane = tid & 31;
    const int gid  = lane >> 2;
    const int t4   = lane & 3;
    const int w32  = warp * 32;

    // Stage Q tile (raw tf32 bits, already scaled)
#pragma unroll
    for (int L = 0; L < 16; L++) {
        int lin = tid + L * 128;
        int row = lin >> 4;
        int c4  = (lin & 15) * 4;
        uint4 v = *(const uint4*)(Qg + (size_t)(q0 + row) * DK_ + c4);
        *(uint4*)(Qs + row * QS_STR + c4) = v;
    }

    float o[2][8][4];
#pragma unroll
    for (int mt = 0; mt < 2; mt++)
#pragma unroll
        for (int nt = 0; nt < 8; nt++)
#pragma unroll
            for (int j = 0; j < 4; j++) o[mt][nt][j] = 0.f;
    float mst[2][2], lst[2][2];
#pragma unroll
    for (int mt = 0; mt < 2; mt++) {
        mst[mt][0] = -1e30f; mst[mt][1] = -1e30f;
        lst[mt][0] = 0.f;    lst[mt][1] = 0.f;
    }

    for (int t0 = 0; t0 < S_; t0 += 64) {
        __syncthreads();  // KV consumers done (also orders Q staging on iter 0)
        // Load K,V tiles (raw copies)
#pragma unroll
        for (int L = 0; L < 8; L++) {
            int lin = tid + L * 128;
            int row = lin >> 4;
            int c4  = (lin & 15) * 4;
            uint4 kv = *(const uint4*)(Kg + (size_t)(t0 + row) * DK_ + c4);
            *(uint4*)(Ks + row * KS_STR + c4) = kv;
            uint4 vv = *(const uint4*)(Vg + (size_t)(t0 + row) * DK_ + c4);
            *(uint4*)(Vs + row * VS_STR + c4) = vv;
        }
        __syncthreads();

        // ---- S = Q @ K^T : warp 32 q-rows x 64 t-cols ----
        float s[2][8][4];
#pragma unroll
        for (int mt = 0; mt < 2; mt++)
#pragma unroll
            for (int nt = 0; nt < 8; nt++)
#pragma unroll
                for (int j = 0; j < 4; j++) s[mt][nt][j] = 0.f;

#pragma unroll
        for (int ks = 0; ks < 8; ks++) {
            uint32_t a[2][4];
#pragma unroll
            for (int mt = 0; mt < 2; mt++) {
                int rb = w32 + mt * 16;
                a[mt][0] = Qs[(rb + gid)     * QS_STR + ks * 8 + t4];
                a[mt][1] = Qs[(rb + gid + 8) * QS_STR + ks * 8 + t4];
                a[mt][2] = Qs[(rb + gid)     * QS_STR + ks * 8 + t4 + 4];
                a[mt][3] = Qs[(rb + gid + 8) * QS_STR + ks * 8 + t4 + 4];
            }
#pragma unroll
            for (int nt = 0; nt < 8; nt++) {
                uint32_t b0 = Ks[(nt * 8 + gid) * KS_STR + ks * 8 + t4];
                uint32_t b1 = Ks[(nt * 8 + gid) * KS_STR + ks * 8 + t4 + 4];
                mma_tf32(s[0][nt], a[0][0], a[0][1], a[0][2], a[0][3], b0, b1);
                mma_tf32(s[1][nt], a[1][0], a[1][1], a[1][2], a[1][3], b0, b1);
            }
        }

        // ---- online softmax (exp2 domain; s already scaled) ----
#pragma unroll
        for (int mt = 0; mt < 2; mt++) {
            float rm0 = -1e30f, rm1 = -1e30f;
#pragma unroll
            for (int nt = 0; nt < 8; nt++) {
                rm0 = fmaxf(rm0, fmaxf(s[mt][nt][0], s[mt][nt][1]));
                rm1 = fmaxf(rm1, fmaxf(s[mt][nt][2], s[mt][nt][3]));
            }
            rm0 = fmaxf(rm0, __shfl_xor_sync(0xffffffffu, rm0, 1));
            rm0 = fmaxf(rm0, __shfl_xor_sync(0xffffffffu, rm0, 2));
            rm1 = fmaxf(rm1, __shfl_xor_sync(0xffffffffu, rm1, 1));
            rm1 = fmaxf(rm1, __shfl_xor_sync(0xffffffffu, rm1, 2));

            float mn0 = fmaxf(mst[mt][0], rm0);
            float mn1 = fmaxf(mst[mt][1], rm1);
            float al0 = exp2f(mst[mt][0] - mn0);
            float al1 = exp2f(mst[mt][1] - mn1);
            mst[mt][0] = mn0; mst[mt][1] = mn1;

            float sum0 = 0.f, sum1 = 0.f;
#pragma unroll
            for (int nt = 0; nt < 8; nt++) {
                float p0 = exp2f(s[mt][nt][0] - mn0);
                float p1 = exp2f(s[mt][nt][1] - mn0);
                float p2 = exp2f(s[mt][nt][2] - mn1);
                float p3 = exp2f(s[mt][nt][3] - mn1);
                sum0 += p0 + p1; sum1 += p2 + p3;
                s[mt][nt][0] = p0; s[mt][nt][1] = p1;
                s[mt][nt][2] = p2; s[mt][nt][3] = p3;
            }
            sum0 += __shfl_xor_sync(0xffffffffu, sum0, 1);
            sum0 += __shfl_xor_sync(0xffffffffu, sum0, 2);
            sum1 += __shfl_xor_sync(0xffffffffu, sum1, 1);
            sum1 += __shfl_xor_sync(0xffffffffu, sum1, 2);
            lst[mt][0] = lst[mt][0] * al0 + sum0;
            lst[mt][1] = lst[mt][1] * al1 + sum1;

#pragma unroll
            for (int nt = 0; nt < 8; nt++) {
                o[mt][nt][0] *= al0; o[mt][nt][1] *= al0;
                o[mt][nt][2] *= al1; o[mt][nt][3] *= al1;
            }
        }

        // ---- O += P @ V : P repacked from registers via shuffles ----
        const int srcA = (lane & 28) | (t4 >> 1);
        const int srcB = srcA + 2;
#pragma unroll
        for (int ks = 0; ks < 8; ks++) {
            uint32_t a[2][4];
#pragma unroll
            for (int mt = 0; mt < 2; mt++) {
                float c0 = s[mt][ks][0], c1 = s[mt][ks][1];
                float c2 = s[mt][ks][2], c3 = s[mt][ks][3];
                float v0, v1;
                v0 = __shfl_sync(0xffffffffu, c0, srcA);
                v1 = __shfl_sync(0xffffffffu, c1, srcA);
                a[mt][0] = f2tf((t4 & 1) ? v1 : v0);
                v0 = __shfl_sync(0xffffffffu, c2, srcA);
                v1 = __shfl_sync(0xffffffffu, c3, srcA);
                a[mt][1] = f2tf((t4 & 1) ? v1 : v0);
                v0 = __shfl_sync(0xffffffffu, c0, srcB);
                v1 = __shfl_sync(0xffffffffu, c1, srcB);
                a[mt][2] = f2tf((t4 & 1) ? v1 : v0);
                v0 = __shfl_sync(0xffffffffu, c2, srcB);
                v1 = __shfl_sync(0xffffffffu, c3, srcB);
                a[mt][3] = f2tf((t4 & 1) ? v1 : v0);
            }
#pragma unroll
            for (int nt = 0; nt < 8; nt++) {
                uint32_t b0 = Vs[(ks * 8 + t4)     * VS_STR + nt * 8 + gid];
                uint32_t b1 = Vs[(ks * 8 + t4 + 4) * VS_STR + nt * 8 + gid];
                mma_tf32(o[0][nt], a[0][0], a[0][1], a[0][2], a[0][3], b0, b1);
                mma_tf32(o[1][nt], a[1][0], a[1][1], a[1][2], a[1][3], b0, b1);
            }
        }
    }

    // Finalize: /l, cvt tf32, store concat layout
    const int b = bh / H_;
    const int h = bh % H_;
#pragma unroll
    for (int mt = 0; mt < 2; mt++) {
        float inv0 = 1.0f / lst[mt][0];
        float inv1 = 1.0f / lst[mt][1];
        int r0 = q0 + w32 + mt * 16 + gid;
        int r1 = r0 + 8;
#pragma unroll
        for (int nt = 0; nt < 8; nt++) {
            int col = nt * 8 + 2 * t4;
            uint2 w0 = make_uint2(f2tf(o[mt][nt][0] * inv0), f2tf(o[mt][nt][1] * inv0));
            uint2 w1 = make_uint2(f2tf(o[mt][nt][2] * inv1), f2tf(o[mt][nt][3] * inv1));
            *(uint2*)(g_cat + ((size_t)(b * S_ + r0)) * (H_ * DK_) + h * DK_ + col) = w0;
            *(uint2*)(g_cat + ((size_t)(b * S_ + r1)) * (H_ * DK_) + h * DK_ + col) = w1;
        }
    }
}

// ---------------------------------------------------------------------------
// Kernel 3: output projection. cat(tf32)[8192,1024] @ Wo[1024,1024] + bo.
// Block 256x64, 8 warps, warp 32x64. grid=(32,16).
// ---------------------------------------------------------------------------
__global__ __launch_bounds__(256) void out_mma_kernel(
    float* __restrict__ out,
    const float* __restrict__ Wo, const float* __restrict__ bo)
{
    __shared__ uint32_t Xs[256 * XS_STR];
    __shared__ uint32_t Ws[32 * WS_STR];

    const int m0 = blockIdx.x * 256;
    const int n0 = blockIdx.y * 64;
    const int tid  = threadIdx.x;
    const int warp = tid >> 5;
    const int lane = tid & 31;
    const int gid  = lane >> 2;
    const int t4   = lane & 3;
    const int w32  = warp * 32;

    float acc[2][8][4];
#pragma unroll
    for (int mt = 0; mt < 2; mt++)
#pragma unroll
        for (int nt = 0; nt < 8; nt++)
#pragma unroll
            for (int j = 0; j < 4; j++) acc[mt][nt][j] = 0.f;

    for (int k0 = 0; k0 < H_ * DK_; k0 += 32) {
        // A tile [256 x 32], raw tf32 bits
#pragma unroll
        for (int L = 0; L < 8; L++) {
            int lin = tid + L * 256;
            int row = lin >> 3;
            int c4  = (lin & 7) * 4;
            uint4 v = *(const uint4*)(g_cat + (size_t)(m0 + row) * (H_ * DK_) + k0 + c4);
            *(uint4*)(Xs + row * XS_STR + c4) = v;
        }
        // W tile [32 x 64], cvt
#pragma unroll
        for (int L = 0; L < 2; L++) {
            int lin = tid + L * 256;
            int kr = lin >> 4;
            int n4 = (lin & 15) * 4;
            float4 w = *(const float4*)(Wo + (size_t)(k0 + kr) * DOUT_ + n0 + n4);
            Ws[kr * WS_STR + n4 + 0] = f2tf(w.x);
            Ws[kr * WS_STR + n4 + 1] = f2tf(w.y);
            Ws[kr * WS_STR + n4 + 2] = f2tf(w.z);
            Ws[kr * WS_STR + n4 + 3] = f2tf(w.w);
        }
        __syncthreads();

#pragma unroll
        for (int ks = 0; ks < 4; ks++) {
            uint32_t a[2][4];
#pragma unroll
            for (int mt = 0; mt < 2; mt++) {
                int rb = w32 + mt * 16;
                a[mt][0] = Xs[(rb + gid)     * XS_STR + ks * 8 + t4];
                a[mt][1] = Xs[(rb + gid + 8) * XS_STR + ks * 8 + t4];
                a[mt][2] = Xs[(rb + gid)     * XS_STR + ks * 8 + t4 + 4];
                a[mt][3] = Xs[(rb + gid + 8) * XS_STR + ks * 8 + t4 + 4];
            }
#pragma unroll
            for (int nt = 0; nt < 8; nt++) {
                uint32_t b0 = Ws[(ks * 8 + t4)     * WS_STR + nt * 8 + gid];
                uint32_t b1 = Ws[(ks * 8 + t4 + 4) * WS_STR + nt * 8 + gid];
                mma_tf32(acc[0][nt], a[0][0], a[0][1], a[0][2], a[0][3], b0, b1);
                mma_tf32(acc[1][nt], a[1][0], a[1][1], a[1][2], a[1][3], b0, b1);
            }
        }
        __syncthreads();
    }

#pragma unroll
    for (int nt = 0; nt < 8; nt++) {
        int ncol = n0 + nt * 8 + 2 * t4;
        float bb0 = bo[ncol];
        float bb1 = bo[ncol + 1];
#pragma unroll
        for (int mt = 0; mt < 2; mt++) {
#pragma unroll
            for (int half = 0; half < 2; half++) {
                int gm = m0 + w32 + mt * 16 + gid + half * 8;
                float2 o;
                o.x = acc[mt][nt][half * 2 + 0] + bb0;
                o.y = acc[mt][nt][half * 2 + 1] + bb1;
                *(float2*)(out + (size_t)gm * DOUT_ + ncol) = o;
            }
        }
    }
}

// ---------------------------------------------------------------------------
// Launch
// ---------------------------------------------------------------------------
extern "C" void kernel_launch(void* const* d_in, const int* in_sizes, int n_in,
                              void* d_out, int out_size)
{
    const float* x  = (const float*)d_in[0];
    const float* Wq = (const float*)d_in[1];
    const float* bq = (const float*)d_in[2];
    const float* Wk = (const float*)d_in[3];
    const float* bk = (const float*)d_in[4];
    const float* Wv = (const float*)d_in[5];
    const float* bv = (const float*)d_in[6];
    const float* Wo = (const float*)d_in[7];
    const float* bo = (const float*)d_in[8];
    float* out = (float*)d_out;

    const int attn_smem = ATTN_SMEM_WORDS * (int)sizeof(uint32_t);  // 70656 B
    cudaFuncSetAttribute(attn_mma_kernel,
                         cudaFuncAttributeMaxDynamicSharedMemorySize, attn_smem);

    dim3 g1(MROWS / 128, H_);
    qkv3_kernel<<<g1, 256>>>(x, Wq, bq, Wk, bk, Wv, bv);

    dim3 g2(S_ / 128, B_ * H_);
    attn_mma_kernel<<<g2, 128, attn_smem>>>();

    dim3 g3(MROWS / 256, DOUT_ / 64);
    out_mma_kernel<<<g3, 256>>>(out, Wo, bo);
}

// round 7
// speedup vs baseline: 1.2128x; 1.2128x over previous
#include <cuda_runtime.h>
#include <math.h>
#include <stdint.h>

// Problem constants
#define B_    4
#define S_    2048
#define D_    1024
#define H_    16
#define DK_   64
#define DOUT_ 1024
#define MROWS (B_ * S_)   // 8192

// Q pre-scale: 1/sqrt(64) * log2(e)
#define QSCALE 0.18033688011112042f

// Scratch (tf32 bit patterns)
__device__ uint32_t g_X[(size_t)MROWS * D_];            // x converted
__device__ uint32_t g_Wqkv[3][(size_t)H_ * D_ * DK_];   // Wq,Wk,Wv converted
__device__ uint32_t g_Wo32[(size_t)D_ * DOUT_];         // Wo converted
__device__ uint32_t g_Q[(size_t)B_ * H_ * S_ * DK_];    // [B,H,S,DK] tf32, pre-scaled
__device__ uint32_t g_K[(size_t)B_ * H_ * S_ * DK_];
__device__ uint32_t g_V[(size_t)B_ * H_ * S_ * DK_];
__device__ uint32_t g_cat[(size_t)B_ * S_ * H_ * DK_];  // [B,S,H*DK] tf32

// ---------------------------------------------------------------------------
// Helpers
// ---------------------------------------------------------------------------
__device__ __forceinline__ uint32_t f2tf(float f) {
    uint32_t u;
    asm("cvt.rna.tf32.f32 %0, %1;" : "=r"(u) : "f"(f));
    return u;
}

__device__ __forceinline__ void mma_tf32(float* d,
                                         uint32_t a0, uint32_t a1, uint32_t a2, uint32_t a3,
                                         uint32_t b0, uint32_t b1) {
    asm volatile(
        "mma.sync.aligned.m16n8k8.row.col.f32.tf32.tf32.f32 "
        "{%0,%1,%2,%3}, {%4,%5,%6,%7}, {%8,%9}, {%0,%1,%2,%3};"
        : "+f"(d[0]), "+f"(d[1]), "+f"(d[2]), "+f"(d[3])
        : "r"(a0), "r"(a1), "r"(a2), "r"(a3), "r"(b0), "r"(b1));
}

__device__ __forceinline__ void cp16(uint32_t smem_addr, const void* gptr) {
    asm volatile("cp.async.cg.shared.global [%0], [%1], 16;"
                 :: "r"(smem_addr), "l"(gptr) : "memory");
}
__device__ __forceinline__ void cp_commit() {
    asm volatile("cp.async.commit_group;" ::: "memory");
}
__device__ __forceinline__ void cp_wait0() {
    asm volatile("cp.async.wait_group 0;" ::: "memory");
}
__device__ __forceinline__ void cp_wait1() {
    asm volatile("cp.async.wait_group 1;" ::: "memory");
}
__device__ __forceinline__ uint32_t s2u(const void* p) {
    return (uint32_t)__cvta_generic_to_shared(p);
}

// ---------------------------------------------------------------------------
// Kernel 0: fp32 -> tf32-bits conversions. Each kernel writes its own
// __device__ symbol directly (no host-side symbol address queries).
// ---------------------------------------------------------------------------
__device__ __forceinline__ void cvt_loop(const float4* __restrict__ src,
                                         uint4* __restrict__ dst, int n4)
{
    int i = blockIdx.x * blockDim.x + threadIdx.x;
    int stride = gridDim.x * blockDim.x;
    for (; i < n4; i += stride) {
        float4 v = src[i];
        dst[i] = make_uint4(f2tf(v.x), f2tf(v.y), f2tf(v.z), f2tf(v.w));
    }
}

__global__ __launch_bounds__(256) void cvt_x_kernel(const float4* __restrict__ src) {
    cvt_loop(src, (uint4*)g_X, (MROWS * D_) / 4);
}
__global__ __launch_bounds__(256) void cvt_wq_kernel(const float4* __restrict__ src) {
    cvt_loop(src, (uint4*)g_Wqkv[0], (H_ * D_ * DK_) / 4);
}
__global__ __launch_bounds__(256) void cvt_wk_kernel(const float4* __restrict__ src) {
    cvt_loop(src, (uint4*)g_Wqkv[1], (H_ * D_ * DK_) / 4);
}
__global__ __launch_bounds__(256) void cvt_wv_kernel(const float4* __restrict__ src) {
    cvt_loop(src, (uint4*)g_Wqkv[2], (H_ * D_ * DK_) / 4);
}
__global__ __launch_bounds__(256) void cvt_wo_kernel(const float4* __restrict__ src) {
    cvt_loop(src, (uint4*)g_Wo32, (D_ * DOUT_) / 4);
}

#define XS_STR 36
#define WS_STR 72

// ---------------------------------------------------------------------------
// Kernel 1: QKV projection (split by type, cp.async double-buffered).
// grid=(64,16,3), 256 threads, block tile 128x64, warp tile 32x32.
// ---------------------------------------------------------------------------
#define QKV_SMEM_WORDS (2 * 128 * XS_STR + 2 * 32 * WS_STR)

__global__ __launch_bounds__(256) void qkv_kernel(
    const float* __restrict__ bq, const float* __restrict__ bk,
    const float* __restrict__ bv)
{
    extern __shared__ uint32_t smw[];
    uint32_t* Xs = smw;                       // [2][128*XS_STR]
    uint32_t* Ws = smw + 2 * 128 * XS_STR;    // [2][32*WS_STR]
    const uint32_t xs_b = s2u(Xs);
    const uint32_t ws_b = s2u(Ws);

    const int type = blockIdx.z;
    const int h  = blockIdx.y;
    const int m0 = blockIdx.x * 128;
    const int tid  = threadIdx.x;
    const int warp = tid >> 5;
    const int lane = tid & 31;
    const int gid  = lane >> 2;
    const int t4   = lane & 3;
    const int wm   = warp >> 1;    // 0..3
    const int wn   = warp & 1;     // 0..1

    const uint32_t* Wh = g_Wqkv[type] + (size_t)h * D_ * DK_;
    const float* bias  = (type == 0) ? bq : (type == 1) ? bk : bv;
    uint32_t* outp     = (type == 0) ? g_Q : (type == 1) ? g_K : g_V;

    // per-thread cp.async slices
    const int xrow = tid >> 3;             // 0..31 (x4 -> 128 rows via L)
    const int xc4  = (tid & 7) * 4;
    const int wkr  = tid >> 4;             // 0..15 (x2 -> 32 rows)
    const int wn4  = (tid & 15) * 4;

    auto issue = [&](int k0, int st) {
#pragma unroll
        for (int L = 0; L < 4; L++) {
            int row = xrow + L * 32;
            cp16(xs_b + (uint32_t)(st * 128 * XS_STR + row * XS_STR + xc4) * 4,
                 g_X + (size_t)(m0 + row) * D_ + k0 + xc4);
        }
#pragma unroll
        for (int L = 0; L < 2; L++) {
            int kr = wkr + L * 16;
            cp16(ws_b + (uint32_t)(st * 32 * WS_STR + kr * WS_STR + wn4) * 4,
                 Wh + (size_t)(k0 + kr) * DK_ + wn4);
        }
        cp_commit();
    };

    float acc[2][4][4];
#pragma unroll
    for (int mt = 0; mt < 2; mt++)
#pragma unroll
        for (int nt = 0; nt < 4; nt++)
#pragma unroll
            for (int j = 0; j < 4; j++) acc[mt][nt][j] = 0.f;

    issue(0, 0);
    int st = 0;
    for (int k0 = 0; k0 < D_; k0 += 32) {
        if (k0 + 32 < D_) { issue(k0 + 32, st ^ 1); cp_wait1(); }
        else              { cp_wait0(); }
        __syncthreads();

        const uint32_t* Xc = Xs + st * 128 * XS_STR;
        const uint32_t* Wc = Ws + st * 32 * WS_STR;
#pragma unroll
        for (int ks = 0; ks < 4; ks++) {
            uint32_t a[2][4];
#pragma unroll
            for (int mt = 0; mt < 2; mt++) {
                int rb = wm * 32 + mt * 16;
                a[mt][0] = Xc[(rb + gid)     * XS_STR + ks * 8 + t4];
                a[mt][1] = Xc[(rb + gid + 8) * XS_STR + ks * 8 + t4];
                a[mt][2] = Xc[(rb + gid)     * XS_STR + ks * 8 + t4 + 4];
                a[mt][3] = Xc[(rb + gid + 8) * XS_STR + ks * 8 + t4 + 4];
            }
#pragma unroll
            for (int nt = 0; nt < 4; nt++) {
                int n = wn * 32 + nt * 8 + gid;
                uint32_t b0 = Wc[(ks * 8 + t4)     * WS_STR + n];
                uint32_t b1 = Wc[(ks * 8 + t4 + 4) * WS_STR + n];
                mma_tf32(acc[0][nt], a[0][0], a[0][1], a[0][2], a[0][3], b0, b1);
                mma_tf32(acc[1][nt], a[1][0], a[1][1], a[1][2], a[1][3], b0, b1);
            }
        }
        __syncthreads();
        st ^= 1;
    }

    // Epilogue: +bias, (Q: *QSCALE), cvt tf32, store to [B,H,S,DK]
#pragma unroll
    for (int nt = 0; nt < 4; nt++) {
        int bcol = wn * 32 + nt * 8 + 2 * t4;
        float bb0 = bias[h * DK_ + bcol];
        float bb1 = bias[h * DK_ + bcol + 1];
#pragma unroll
        for (int mt = 0; mt < 2; mt++) {
#pragma unroll
            for (int half = 0; half < 2; half++) {
                int gm = m0 + wm * 32 + mt * 16 + gid + half * 8;
                int bb = gm >> 11;
                int s  = gm & 2047;
                float v0 = acc[mt][nt][half * 2 + 0] + bb0;
                float v1 = acc[mt][nt][half * 2 + 1] + bb1;
                if (type == 0) { v0 *= QSCALE; v1 *= QSCALE; }
                uint2 o = make_uint2(f2tf(v0), f2tf(v1));
                *(uint2*)(outp + ((size_t)(bb * H_ + h) * S_ + s) * DK_ + bcol) = o;
            }
        }
    }
}

// ---------------------------------------------------------------------------
// Kernel 2: flash attention, cp.async double-buffered K/V.
// 128 threads (4 warps), 128 q-rows/block, warp = 32 rows, register P.
// ---------------------------------------------------------------------------
#define QS_STR 68
#define KS_STR 68
#define VS_STR 72
#define ATTN_SMEM_WORDS (128 * QS_STR + 2 * 64 * KS_STR + 2 * 64 * VS_STR)

__global__ __launch_bounds__(128) void attn_mma_kernel()
{
    extern __shared__ uint32_t smw[];
    uint32_t* Qs  = smw;                              // [128][QS_STR]
    uint32_t* Ksb = Qs + 128 * QS_STR;                // [2][64*KS_STR]
    uint32_t* Vsb = Ksb + 2 * 64 * KS_STR;            // [2][64*VS_STR]
    const uint32_t ks_b = s2u(Ksb);
    const uint32_t vs_b = s2u(Vsb);

    const int bh = blockIdx.y;
    const int q0 = blockIdx.x * 128;
    const uint32_t* Qg = g_Q + (size_t)bh * S_ * DK_;
    const uint32_t* Kg = g_K + (size_t)bh * S_ * DK_;
    const uint32_t* Vg = g_V + (size_t)bh * S_ * DK_;

    const int tid  = threadIdx.x;
    const int warp = tid >> 5;
    const int lane = tid & 31;
    const int gid  = lane >> 2;
    const int t4   = lane & 3;
    const int w32  = warp * 32;

    const int kvrow = tid >> 4;          // 0..7 (x8 -> 64 rows)
    const int kvc4  = (tid & 15) * 4;

    auto issueKV = [&](int t0, int st) {
#pragma unroll
        for (int L = 0; L < 8; L++) {
            int row = kvrow + L * 8;
            cp16(ks_b + (uint32_t)(st * 64 * KS_STR + row * KS_STR + kvc4) * 4,
                 Kg + (size_t)(t0 + row) * DK_ + kvc4);
            cp16(vs_b + (uint32_t)(st * 64 * VS_STR + row * VS_STR + kvc4) * 4,
                 Vg + (size_t)(t0 + row) * DK_ + kvc4);
        }
        cp_commit();
    };

    issueKV(0, 0);

    // Stage Q tile (raw tf32 bits, pre-scaled)
#pragma unroll
    for (int L = 0; L < 16; L++) {
        int lin = tid + L * 128;
        int row = lin >> 4;
        int c4  = (lin & 15) * 4;
        uint4 v = *(const uint4*)(Qg + (size_t)(q0 + row) * DK_ + c4);
        *(uint4*)(Qs + row * QS_STR + c4) = v;
    }

    float o[2][8][4];
#pragma unroll
    for (int mt = 0; mt < 2; mt++)
#pragma unroll
        for (int nt = 0; nt < 8; nt++)
#pragma unroll
            for (int j = 0; j < 4; j++) o[mt][nt][j] = 0.f;
    float mst[2][2], lst[2][2];
#pragma unroll
    for (int mt = 0; mt < 2; mt++) {
        mst[mt][0] = -1e30f; mst[mt][1] = -1e30f;
        lst[mt][0] = 0.f;    lst[mt][1] = 0.f;
    }

    int st = 0;
    for (int t0 = 0; t0 < S_; t0 += 64) {
        if (t0 + 64 < S_) { issueKV(t0 + 64, st ^ 1); cp_wait1(); }
        else              { cp_wait0(); }
        __syncthreads();   // KV tile visible; also orders Q staging (iter 0)

        const uint32_t* Ks = Ksb + st * 64 * KS_STR;
        const uint32_t* Vs = Vsb + st * 64 * VS_STR;

        // ---- S = Q @ K^T ----
        float s[2][8][4];
#pragma unroll
        for (int mt = 0; mt < 2; mt++)
#pragma unroll
            for (int nt = 0; nt < 8; nt++)
#pragma unroll
                for (int j = 0; j < 4; j++) s[mt][nt][j] = 0.f;

#pragma unroll
        for (int ks = 0; ks < 8; ks++) {
            uint32_t a[2][4];
#pragma unroll
            for (int mt = 0; mt < 2; mt++) {
                int rb = w32 + mt * 16;
                a[mt][0] = Qs[(rb + gid)     * QS_STR + ks * 8 + t4];
                a[mt][1] = Qs[(rb + gid + 8) * QS_STR + ks * 8 + t4];
                a[mt][2] = Qs[(rb + gid)     * QS_STR + ks * 8 + t4 + 4];
                a[mt][3] = Qs[(rb + gid + 8) * QS_STR + ks * 8 + t4 + 4];
            }
#pragma unroll
            for (int nt = 0; nt < 8; nt++) {
                uint32_t b0 = Ks[(nt * 8 + gid) * KS_STR + ks * 8 + t4];
                uint32_t b1 = Ks[(nt * 8 + gid) * KS_STR + ks * 8 + t4 + 4];
                mma_tf32(s[0][nt], a[0][0], a[0][1], a[0][2], a[0][3], b0, b1);
                mma_tf32(s[1][nt], a[1][0], a[1][1], a[1][2], a[1][3], b0, b1);
            }
        }

        // ---- online softmax (exp2 domain) ----
#pragma unroll
        for (int mt = 0; mt < 2; mt++) {
            float rm0 = -1e30f, rm1 = -1e30f;
#pragma unroll
            for (int nt = 0; nt < 8; nt++) {
                rm0 = fmaxf(rm0, fmaxf(s[mt][nt][0], s[mt][nt][1]));
                rm1 = fmaxf(rm1, fmaxf(s[mt][nt][2], s[mt][nt][3]));
            }
            rm0 = fmaxf(rm0, __shfl_xor_sync(0xffffffffu, rm0, 1));
            rm0 = fmaxf(rm0, __shfl_xor_sync(0xffffffffu, rm0, 2));
            rm1 = fmaxf(rm1, __shfl_xor_sync(0xffffffffu, rm1, 1));
            rm1 = fmaxf(rm1, __shfl_xor_sync(0xffffffffu, rm1, 2));

            float mn0 = fmaxf(mst[mt][0], rm0);
            float mn1 = fmaxf(mst[mt][1], rm1);
            float al0 = exp2f(mst[mt][0] - mn0);
            float al1 = exp2f(mst[mt][1] - mn1);
            mst[mt][0] = mn0; mst[mt][1] = mn1;

            float sum0 = 0.f, sum1 = 0.f;
#pragma unroll
            for (int nt = 0; nt < 8; nt++) {
                float p0 = exp2f(s[mt][nt][0] - mn0);
                float p1 = exp2f(s[mt][nt][1] - mn0);
                float p2 = exp2f(s[mt][nt][2] - mn1);
                float p3 = exp2f(s[mt][nt][3] - mn1);
                sum0 += p0 + p1; sum1 += p2 + p3;
                s[mt][nt][0] = p0; s[mt][nt][1] = p1;
                s[mt][nt][2] = p2; s[mt][nt][3] = p3;
            }
            sum0 += __shfl_xor_sync(0xffffffffu, sum0, 1);
            sum0 += __shfl_xor_sync(0xffffffffu, sum0, 2);
            sum1 += __shfl_xor_sync(0xffffffffu, sum1, 1);
            sum1 += __shfl_xor_sync(0xffffffffu, sum1, 2);
            lst[mt][0] = lst[mt][0] * al0 + sum0;
            lst[mt][1] = lst[mt][1] * al1 + sum1;

#pragma unroll
            for (int nt = 0; nt < 8; nt++) {
                o[mt][nt][0] *= al0; o[mt][nt][1] *= al0;
                o[mt][nt][2] *= al1; o[mt][nt][3] *= al1;
            }
        }

        // ---- O += P @ V (register repack via shuffles) ----
        const int srcA = (lane & 28) | (t4 >> 1);
        const int srcB = srcA + 2;
#pragma unroll
        for (int ks = 0; ks < 8; ks++) {
            uint32_t a[2][4];
#pragma unroll
            for (int mt = 0; mt < 2; mt++) {
                float c0 = s[mt][ks][0], c1 = s[mt][ks][1];
                float c2 = s[mt][ks][2], c3 = s[mt][ks][3];
                float v0, v1;
                v0 = __shfl_sync(0xffffffffu, c0, srcA);
                v1 = __shfl_sync(0xffffffffu, c1, srcA);
                a[mt][0] = f2tf((t4 & 1) ? v1 : v0);
                v0 = __shfl_sync(0xffffffffu, c2, srcA);
                v1 = __shfl_sync(0xffffffffu, c3, srcA);
                a[mt][1] = f2tf((t4 & 1) ? v1 : v0);
                v0 = __shfl_sync(0xffffffffu, c0, srcB);
                v1 = __shfl_sync(0xffffffffu, c1, srcB);
                a[mt][2] = f2tf((t4 & 1) ? v1 : v0);
                v0 = __shfl_sync(0xffffffffu, c2, srcB);
                v1 = __shfl_sync(0xffffffffu, c3, srcB);
                a[mt][3] = f2tf((t4 & 1) ? v1 : v0);
            }
#pragma unroll
            for (int nt = 0; nt < 8; nt++) {
                uint32_t b0 = Vs[(ks * 8 + t4)     * VS_STR + nt * 8 + gid];
                uint32_t b1 = Vs[(ks * 8 + t4 + 4) * VS_STR + nt * 8 + gid];
                mma_tf32(o[0][nt], a[0][0], a[0][1], a[0][2], a[0][3], b0, b1);
                mma_tf32(o[1][nt], a[1][0], a[1][1], a[1][2], a[1][3], b0, b1);
            }
        }
        __syncthreads();   // all readers done; buffer st free for prefetch
        st ^= 1;
    }

    // Finalize
    const int b = bh / H_;
    const int h = bh % H_;
#pragma unroll
    for (int mt = 0; mt < 2; mt++) {
        float inv0 = 1.0f / lst[mt][0];
        float inv1 = 1.0f / lst[mt][1];
        int r0 = q0 + w32 + mt * 16 + gid;
        int r1 = r0 + 8;
#pragma unroll
        for (int nt = 0; nt < 8; nt++) {
            int col = nt * 8 + 2 * t4;
            uint2 w0 = make_uint2(f2tf(o[mt][nt][0] * inv0), f2tf(o[mt][nt][1] * inv0));
            uint2 w1 = make_uint2(f2tf(o[mt][nt][2] * inv1), f2tf(o[mt][nt][3] * inv1));
            *(uint2*)(g_cat + ((size_t)(b * S_ + r0)) * (H_ * DK_) + h * DK_ + col) = w0;
            *(uint2*)(g_cat + ((size_t)(b * S_ + r1)) * (H_ * DK_) + h * DK_ + col) = w1;
        }
    }
}

// ---------------------------------------------------------------------------
// Kernel 3: output projection, cp.async double-buffered.
// Block tile 256x64, 8 warps, warp 32x64. grid=(32,16).
// ---------------------------------------------------------------------------
#define OUT_SMEM_WORDS (2 * 256 * XS_STR + 2 * 32 * WS_STR)

__global__ __launch_bounds__(256) void out_mma_kernel(
    float* __restrict__ out, const float* __restrict__ bo)
{
    extern __shared__ uint32_t smw[];
    uint32_t* Xs = smw;                        // [2][256*XS_STR]
    uint32_t* Ws = smw + 2 * 256 * XS_STR;     // [2][32*WS_STR]
    const uint32_t xs_b = s2u(Xs);
    const uint32_t ws_b = s2u(Ws);

    const int m0 = blockIdx.x * 256;
    const int n0 = blockIdx.y * 64;
    const int tid  = threadIdx.x;
    const int warp = tid >> 5;
    const int lane = tid & 31;
    const int gid  = lane >> 2;
    const int t4   = lane & 3;
    const int w32  = warp * 32;

    const int xrow = tid >> 3;           // 0..31 (x8 -> 256 rows)
    const int xc4  = (tid & 7) * 4;
    const int wkr  = tid >> 4;           // 0..15 (x2 -> 32 rows)
    const int wn4  = (tid & 15) * 4;

    auto issue = [&](int k0, int st) {
#pragma unroll
        for (int L = 0; L < 8; L++) {
            int row = xrow + L * 32;
            cp16(xs_b + (uint32_t)(st * 256 * XS_STR + row * XS_STR + xc4) * 4,
                 g_cat + (size_t)(m0 + row) * (H_ * DK_) + k0 + xc4);
        }
#pragma unroll
        for (int L = 0; L < 2; L++) {
            int kr = wkr + L * 16;
            cp16(ws_b + (uint32_t)(st * 32 * WS_STR + kr * WS_STR + wn4) * 4,
                 g_Wo32 + (size_t)(k0 + kr) * DOUT_ + n0 + wn4);
        }
        cp_commit();
    };

    float acc[2][8][4];
#pragma unroll
    for (int mt = 0; mt < 2; mt++)
#pragma unroll
        for (int nt = 0; nt < 8; nt++)
#pragma unroll
            for (int j = 0; j < 4; j++) acc[mt][nt][j] = 0.f;

    issue(0, 0);
    int st = 0;
    for (int k0 = 0; k0 < H_ * DK_; k0 += 32) {
        if (k0 + 32 < H_ * DK_) { issue(k0 + 32, st ^ 1); cp_wait1(); }
        else                    { cp_wait0(); }
        __syncthreads();

        const uint32_t* Xc = Xs + st * 256 * XS_STR;
        const uint32_t* Wc = Ws + st * 32 * WS_STR;
#pragma unroll
        for (int ks = 0; ks < 4; ks++) {
            uint32_t a[2][4];
#pragma unroll
            for (int mt = 0; mt < 2; mt++) {
                int rb = w32 + mt * 16;
                a[mt][0] = Xc[(rb + gid)     * XS_STR + ks * 8 + t4];
                a[mt][1] = Xc[(rb + gid + 8) * XS_STR + ks * 8 + t4];
                a[mt][2] = Xc[(rb + gid)     * XS_STR + ks * 8 + t4 + 4];
                a[mt][3] = Xc[(rb + gid + 8) * XS_STR + ks * 8 + t4 + 4];
            }
#pragma unroll
            for (int nt = 0; nt < 8; nt++) {
                uint32_t b0 = Wc[(ks * 8 + t4)     * WS_STR + nt * 8 + gid];
                uint32_t b1 = Wc[(ks * 8 + t4 + 4) * WS_STR + nt * 8 + gid];
                mma_tf32(acc[0][nt], a[0][0], a[0][1], a[0][2], a[0][3], b0, b1);
                mma_tf32(acc[1][nt], a[1][0], a[1][1], a[1][2], a[1][3], b0, b1);
            }
        }
        __syncthreads();
        st ^= 1;
    }

#pragma unroll
    for (int nt = 0; nt < 8; nt++) {
        int ncol = n0 + nt * 8 + 2 * t4;
        float bb0 = bo[ncol];
        float bb1 = bo[ncol + 1];
#pragma unroll
        for (int mt = 0; mt < 2; mt++) {
#pragma unroll
            for (int half = 0; half < 2; half++) {
                int gm = m0 + w32 + mt * 16 + gid + half * 8;
                float2 o;
                o.x = acc[mt][nt][half * 2 + 0] + bb0;
                o.y = acc[mt][nt][half * 2 + 1] + bb1;
                *(float2*)(out + (size_t)gm * DOUT_ + ncol) = o;
            }
        }
    }
}

// ---------------------------------------------------------------------------
// Launch
// ---------------------------------------------------------------------------
extern "C" void kernel_launch(void* const* d_in, const int* in_sizes, int n_in,
                              void* d_out, int out_size)
{
    const float* x  = (const float*)d_in[0];
    const float* Wq = (const float*)d_in[1];
    const float* bq = (const float*)d_in[2];
    const float* Wk = (const float*)d_in[3];
    const float* bk = (const float*)d_in[4];
    const float* Wv = (const float*)d_in[5];
    const float* bv = (const float*)d_in[6];
    const float* Wo = (const float*)d_in[7];
    const float* bo = (const float*)d_in[8];
    float* out = (float*)d_out;

    const int qkv_smem  = QKV_SMEM_WORDS  * (int)sizeof(uint32_t);  // 55296
    const int attn_smem = ATTN_SMEM_WORDS * (int)sizeof(uint32_t);  // 106496
    const int out_smem  = OUT_SMEM_WORDS  * (int)sizeof(uint32_t);  // 92160
    cudaFuncSetAttribute(qkv_kernel,
                         cudaFuncAttributeMaxDynamicSharedMemorySize, qkv_smem);
    cudaFuncSetAttribute(attn_mma_kernel,
                         cudaFuncAttributeMaxDynamicSharedMemorySize, attn_smem);
    cudaFuncSetAttribute(out_mma_kernel,
                         cudaFuncAttributeMaxDynamicSharedMemorySize, out_smem);

    // Pre-convert inputs to tf32 bit buffers (device symbols written directly)
    cvt_x_kernel <<<2048, 256>>>((const float4*)x);
    cvt_wq_kernel<<<1024, 256>>>((const float4*)Wq);
    cvt_wk_kernel<<<1024, 256>>>((const float4*)Wk);
    cvt_wv_kernel<<<1024, 256>>>((const float4*)Wv);
    cvt_wo_kernel<<<1024, 256>>>((const float4*)Wo);

    dim3 g1(MROWS / 128, H_, 3);
    qkv_kernel<<<g1, 256, qkv_smem>>>(bq, bk, bv);

    dim3 g2(S_ / 128, B_ * H_);
    attn_mma_kernel<<<g2, 128, attn_smem>>>();

    dim3 g3(MROWS / 256, DOUT_ / 64);
    out_mma_kernel<<<g3, 256, out_smem>>>(out, bo);
}